// round 2
// baseline (speedup 1.0000x reference)
#include <cuda_runtime.h>
#include <cuda_bf16.h>
#include <cuda_fp8.h>
#include <cstdint>

#define MDIM 16384
#define KDIM 2048
#define NDIM 2048

#define BM 128
#define BN 128
#define BK 32
#define KITERS (KDIM / BK)   // 64
#define STAGES 4
#define ROWB 80              // padded row pitch in bytes (32 bf16 = 64B data + 16B pad)
#define STAGE_BYTES (2 * BM * ROWB)   // A tile + B tile = 20480
#define GEMM_SMEM (STAGES * STAGE_BYTES)  // 81920

// ---------------- device scratch (allocation-free rule) ----------------------
__device__ __align__(16) __nv_bfloat16 g_qa[(size_t)MDIM * KDIM]; // 64 MB
__device__ __align__(16) __nv_bfloat16 g_qb[(size_t)NDIM * KDIM]; // 8 MB
__device__ unsigned g_amax_bits;

// ---------------- helpers ----------------------------------------------------
__device__ __forceinline__ uint32_t smem_u32(const void* p) {
    uint32_t a;
    asm("{ .reg .u64 t; cvta.to.shared.u64 t, %1; cvt.u32.u64 %0, t; }"
        : "=r"(a) : "l"(p));
    return a;
}

#define CP_ASYNC16(smem, gptr) \
    asm volatile("cp.async.cg.shared.global [%0], [%1], 16;" \
                 :: "r"(smem), "l"(gptr) : "memory")
#define CP_COMMIT() asm volatile("cp.async.commit_group;" ::: "memory")
#define CP_WAIT(n)  asm volatile("cp.async.wait_group %0;" :: "n"(n) : "memory")

#define LDSM_X4(r0, r1, r2, r3, addr) \
    asm volatile("ldmatrix.sync.aligned.m8n8.x4.shared.b16 {%0,%1,%2,%3}, [%4];" \
                 : "=r"(r0), "=r"(r1), "=r"(r2), "=r"(r3) : "r"(addr))

#define MMA16816(c, a, b0, b1) \
    asm volatile("mma.sync.aligned.m16n8k16.row.col.f32.bf16.bf16.f32 " \
                 "{%0,%1,%2,%3}, {%4,%5,%6,%7}, {%8,%9}, {%0,%1,%2,%3};" \
                 : "+f"((c)[0]), "+f"((c)[1]), "+f"((c)[2]), "+f"((c)[3]) \
                 : "r"((a)[0]), "r"((a)[1]), "r"((a)[2]), "r"((a)[3]), \
                   "r"(b0), "r"(b1))

// ---------------- phase 1: amax ---------------------------------------------
__global__ void zero_kernel() { g_amax_bits = 0u; }

__global__ void amax_kernel(const float* __restrict__ x, int n4) {
    const float4* x4 = (const float4*)x;
    float m = 0.0f;
    for (int i = blockIdx.x * blockDim.x + threadIdx.x; i < n4; i += gridDim.x * blockDim.x) {
        float4 v = x4[i];
        m = fmaxf(m, fmaxf(fmaxf(fabsf(v.x), fabsf(v.y)), fmaxf(fabsf(v.z), fabsf(v.w))));
    }
    #pragma unroll
    for (int o = 16; o; o >>= 1) m = fmaxf(m, __shfl_xor_sync(0xFFFFFFFFu, m, o));
    __shared__ float sm[32];
    if ((threadIdx.x & 31) == 0) sm[threadIdx.x >> 5] = m;
    __syncthreads();
    if (threadIdx.x < 32) {
        m = (threadIdx.x < (blockDim.x >> 5)) ? sm[threadIdx.x] : 0.0f;
        #pragma unroll
        for (int o = 16; o; o >>= 1) m = fmaxf(m, __shfl_xor_sync(0xFFFFFFFFu, m, o));
        if (threadIdx.x == 0) atomicMax(&g_amax_bits, __float_as_uint(m));
    }
}

// ---------------- phase 2: quantize -----------------------------------------
__device__ __forceinline__ __nv_bfloat16 fp8_round_to_bf16(float v) {
    __nv_fp8_e4m3 q(v);                 // RN + satfinite == clip(+-448) + round in ref
    return __float2bfloat16(float(q));  // e4m3 exactly representable in bf16
}

__global__ void quant_a_kernel(const float* __restrict__ x) {
    int i = blockIdx.x * blockDim.x + threadIdx.x;  // float4 index
    float amax = fmaxf(__uint_as_float(g_amax_bits), 1e-12f);
    float scale = 448.0f / amax;
    float4 v = ((const float4*)x)[i];
    __nv_bfloat162 p0(fp8_round_to_bf16(v.x * scale), fp8_round_to_bf16(v.y * scale));
    __nv_bfloat162 p1(fp8_round_to_bf16(v.z * scale), fp8_round_to_bf16(v.w * scale));
    uint2 o;
    o.x = *reinterpret_cast<uint32_t*>(&p0);
    o.y = *reinterpret_cast<uint32_t*>(&p1);
    ((uint2*)g_qa)[i] = o;
}

__global__ void quant_b_kernel(const float* __restrict__ w) {
    int i = blockIdx.x * blockDim.x + threadIdx.x;  // float4 index
    float4 v = ((const float4*)w)[i];
    __nv_bfloat162 p0(__float2bfloat16(v.x), __float2bfloat16(v.y));  // exact (fp8-grid values)
    __nv_bfloat162 p1(__float2bfloat16(v.z), __float2bfloat16(v.w));
    uint2 o;
    o.x = *reinterpret_cast<uint32_t*>(&p0);
    o.y = *reinterpret_cast<uint32_t*>(&p1);
    ((uint2*)g_qb)[i] = o;
}

// ---------------- phase 3: GEMM (mma.sync bf16, cp.async pipeline) ----------
// SMEM stage layout: A tile [128 rows x 80B], then B tile [128 rows x 80B].
// Row pitch 80B (=5*16B, 5 coprime 8) -> ldmatrix 8-row accesses conflict-free.

__global__ __launch_bounds__(256, 2)
void gemm_kernel(const float* __restrict__ wscale, const float* __restrict__ bias,
                 float* __restrict__ out) {
    extern __shared__ char smem[];
    const uint32_t s0 = smem_u32(smem);

    const int tid = threadIdx.x;
    const int wid = tid >> 5, lane = tid & 31;
    const int warp_m = wid >> 1, warp_n = wid & 1;   // 4 x 2 warps
    const int ntile = blockIdx.x, mtile = blockIdx.y;
    const int quad = lane >> 3, l8 = lane & 7;

    const __nv_bfloat16* Ag = g_qa + (size_t)mtile * BM * KDIM;
    const __nv_bfloat16* Bg = g_qb + (size_t)ntile * BN * KDIM;

    // cp.async mapping: 512 16B-chunks per tile, 2 per thread
    const int c0 = tid, c1 = tid + 256;
    const int ar0 = c0 >> 2, ac0 = c0 & 3;   // row, 16B-chunk within row
    const int ar1 = c1 >> 2, ac1 = c1 & 3;
    const uint32_t sA_off0 = (uint32_t)(ar0 * ROWB + ac0 * 16);
    const uint32_t sA_off1 = (uint32_t)(ar1 * ROWB + ac1 * 16);

    // ldmatrix per-thread offsets (within a stage's A/B tile)
    // A x4: row = warp_m*32 + i*16 + (quad&1)*8 + l8 ; kb = (quad>>1)*16
    uint32_t aoff[2], boff[4];
    #pragma unroll
    for (int i = 0; i < 2; i++)
        aoff[i] = (uint32_t)((warp_m * 32 + i * 16 + (quad & 1) * 8 + l8) * ROWB
                             + (quad >> 1) * 16);
    // B x4: n = warp_n*64 + j*16 + (quad>>1)*8 + l8 ; kb = (quad&1)*16
    #pragma unroll
    for (int j = 0; j < 4; j++)
        boff[j] = (uint32_t)(BM * ROWB
                             + (warp_n * 64 + j * 16 + (quad >> 1) * 8 + l8) * ROWB
                             + (quad & 1) * 16);

    float acc[2][8][4];
    #pragma unroll
    for (int mi = 0; mi < 2; mi++)
        #pragma unroll
        for (int ni = 0; ni < 8; ni++)
            #pragma unroll
            for (int r = 0; r < 4; r++) acc[mi][ni][r] = 0.0f;

    // ---- prologue: fill STAGES-1 stages
    #pragma unroll
    for (int st = 0; st < STAGES - 1; st++) {
        uint32_t sb = s0 + st * STAGE_BYTES;
        const __nv_bfloat16* ga = Ag + st * BK;
        const __nv_bfloat16* gb = Bg + st * BK;
        CP_ASYNC16(sb + sA_off0, ga + (size_t)ar0 * KDIM + ac0 * 8);
        CP_ASYNC16(sb + sA_off1, ga + (size_t)ar1 * KDIM + ac1 * 8);
        CP_ASYNC16(sb + (uint32_t)(BM * ROWB) + sA_off0, gb + (size_t)ar0 * KDIM + ac0 * 8);
        CP_ASYNC16(sb + (uint32_t)(BM * ROWB) + sA_off1, gb + (size_t)ar1 * KDIM + ac1 * 8);
        CP_COMMIT();
    }

    // ---- mainloop
    #pragma unroll 1
    for (int it = 0; it < KITERS; ++it) {
        CP_WAIT(STAGES - 2);
        __syncthreads();

        // issue loads for stage it+STAGES-1
        {
            int lt = it + STAGES - 1;
            if (lt < KITERS) {
                uint32_t sb = s0 + (lt % STAGES) * STAGE_BYTES;
                const __nv_bfloat16* ga = Ag + lt * BK;
                const __nv_bfloat16* gb = Bg + lt * BK;
                CP_ASYNC16(sb + sA_off0, ga + (size_t)ar0 * KDIM + ac0 * 8);
                CP_ASYNC16(sb + sA_off1, ga + (size_t)ar1 * KDIM + ac1 * 8);
                CP_ASYNC16(sb + (uint32_t)(BM * ROWB) + sA_off0, gb + (size_t)ar0 * KDIM + ac0 * 8);
                CP_ASYNC16(sb + (uint32_t)(BM * ROWB) + sA_off1, gb + (size_t)ar1 * KDIM + ac1 * 8);
            }
            CP_COMMIT();   // empty group near the tail keeps wait_group counting uniform
        }

        uint32_t sb = s0 + (it % STAGES) * STAGE_BYTES;
        #pragma unroll
        for (int s = 0; s < 2; s++) {          // two k16 steps per BK=32
            uint32_t a[2][4], b[4][4];
            #pragma unroll
            for (int i = 0; i < 2; i++)
                LDSM_X4(a[i][0], a[i][1], a[i][2], a[i][3], sb + aoff[i] + s * 32);
            #pragma unroll
            for (int j = 0; j < 4; j++)
                LDSM_X4(b[j][0], b[j][1], b[j][2], b[j][3], sb + boff[j] + s * 32);
            #pragma unroll
            for (int mi = 0; mi < 2; mi++)
                #pragma unroll
                for (int ni = 0; ni < 8; ni++)
                    MMA16816(acc[mi][ni], a[mi], b[ni >> 1][(ni & 1) * 2],
                             b[ni >> 1][(ni & 1) * 2 + 1]);
        }
        __syncthreads();
    }

    // ---- epilogue: out = acc * (a_scale * w_scale) + bias
    float amax = fmaxf(__uint_as_float(g_amax_bits), 1e-12f);
    float comb = (amax / 448.0f) * wscale[0];

    const int gid = lane >> 2;          // groupID: row 0..7
    const int lq = lane & 3;
    #pragma unroll
    for (int mi = 0; mi < 2; mi++) {
        int r0 = mtile * BM + warp_m * 32 + mi * 16 + gid;
        #pragma unroll
        for (int ni = 0; ni < 8; ni++) {
            int colg = ntile * BN + warp_n * 64 + ni * 8 + lq * 2;
            float2 bb = *(const float2*)(bias + colg);
            float2 o0, o1;
            o0.x = acc[mi][ni][0] * comb + bb.x;
            o0.y = acc[mi][ni][1] * comb + bb.y;
            o1.x = acc[mi][ni][2] * comb + bb.x;
            o1.y = acc[mi][ni][3] * comb + bb.y;
            *(float2*)(out + (size_t)r0 * NDIM + colg) = o0;
            *(float2*)(out + (size_t)(r0 + 8) * NDIM + colg) = o1;
        }
    }
}

// ---------------- launch -----------------------------------------------------
extern "C" void kernel_launch(void* const* d_in, const int* in_sizes, int n_in,
                              void* d_out, int out_size) {
    const float* input = nullptr;
    const float* qweight = nullptr;
    const float* wscale = nullptr;
    const float* bias = nullptr;
    for (int i = 0; i < n_in; i++) {
        long long s = in_sizes[i];
        if (s == (long long)MDIM * KDIM) input = (const float*)d_in[i];
        else if (s == (long long)NDIM * KDIM) qweight = (const float*)d_in[i];
        else if (s == 1) wscale = (const float*)d_in[i];
        else if (s == NDIM) bias = (const float*)d_in[i];
    }
    float* out = (float*)d_out;

    cudaFuncSetAttribute(gemm_kernel, cudaFuncAttributeMaxDynamicSharedMemorySize,
                         GEMM_SMEM);

    zero_kernel<<<1, 1>>>();
    amax_kernel<<<1024, 256>>>(input, MDIM * KDIM / 4);
    quant_a_kernel<<<MDIM * KDIM / 4 / 256, 256>>>(input);
    quant_b_kernel<<<NDIM * KDIM / 4 / 256, 256>>>(qweight);

    dim3 grid(NDIM / BN, MDIM / BM);   // ntile fastest: weight tile L2-resident
    gemm_kernel<<<grid, 256, GEMM_SMEM>>>(wscale, bias, out);
}

// round 3
// speedup vs baseline: 1.1449x; 1.1449x over previous
#include <cuda_runtime.h>
#include <cuda_bf16.h>
#include <cuda_fp8.h>
#include <cstdint>

#define MDIM 16384
#define KDIM 2048
#define NDIM 2048

#define BM 128
#define BN 128
#define BK 64                // fp8 elems per K-tile = 64 bytes/row
#define KITERS (KDIM / BK)   // 32
#define STAGES 4
#define ROWB 80              // padded row pitch (64B data + 16B pad; 5*16B coprime 8 banks)
#define STAGE_BYTES (2 * BM * ROWB)       // A tile + B tile = 20480
#define GEMM_SMEM (STAGES * STAGE_BYTES)  // 81920

// ---------------- device scratch (allocation-free rule) ----------------------
__device__ __align__(16) uint8_t g_qa[(size_t)MDIM * KDIM]; // 32 MB fp8
__device__ __align__(16) uint8_t g_qb[(size_t)NDIM * KDIM]; // 4 MB fp8
__device__ unsigned g_amax_bits;

// ---------------- helpers ----------------------------------------------------
__device__ __forceinline__ uint32_t smem_u32(const void* p) {
    uint32_t a;
    asm("{ .reg .u64 t; cvta.to.shared.u64 t, %1; cvt.u32.u64 %0, t; }"
        : "=r"(a) : "l"(p));
    return a;
}

#define CP_ASYNC16(smem, gptr) \
    asm volatile("cp.async.cg.shared.global [%0], [%1], 16;" \
                 :: "r"(smem), "l"(gptr) : "memory")
#define CP_COMMIT() asm volatile("cp.async.commit_group;" ::: "memory")
#define CP_WAIT(n)  asm volatile("cp.async.wait_group %0;" :: "n"(n) : "memory")

#define LDSM_X4(r0, r1, r2, r3, addr) \
    asm volatile("ldmatrix.sync.aligned.m8n8.x4.shared.b16 {%0,%1,%2,%3}, [%4];" \
                 : "=r"(r0), "=r"(r1), "=r"(r2), "=r"(r3) : "r"(addr))

// fp8 e4m3 MMA: m16n8k32, fragment layout == bf16 m16n8k16 with b16 elem = 2 fp8
#define MMA16832(c, a, b0, b1) \
    asm volatile("mma.sync.aligned.m16n8k32.row.col.f32.e4m3.e4m3.f32 " \
                 "{%0,%1,%2,%3}, {%4,%5,%6,%7}, {%8,%9}, {%0,%1,%2,%3};" \
                 : "+f"((c)[0]), "+f"((c)[1]), "+f"((c)[2]), "+f"((c)[3]) \
                 : "r"((a)[0]), "r"((a)[1]), "r"((a)[2]), "r"((a)[3]), \
                   "r"(b0), "r"(b1))

// ---------------- phase 1: amax ---------------------------------------------
__global__ void zero_kernel() { g_amax_bits = 0u; }

__global__ void amax_kernel(const float* __restrict__ x, int n4) {
    const float4* x4 = (const float4*)x;
    float m = 0.0f;
    for (int i = blockIdx.x * blockDim.x + threadIdx.x; i < n4; i += gridDim.x * blockDim.x) {
        float4 v = x4[i];
        m = fmaxf(m, fmaxf(fmaxf(fabsf(v.x), fabsf(v.y)), fmaxf(fabsf(v.z), fabsf(v.w))));
    }
    #pragma unroll
    for (int o = 16; o; o >>= 1) m = fmaxf(m, __shfl_xor_sync(0xFFFFFFFFu, m, o));
    __shared__ float sm[32];
    if ((threadIdx.x & 31) == 0) sm[threadIdx.x >> 5] = m;
    __syncthreads();
    if (threadIdx.x < 32) {
        m = (threadIdx.x < (blockDim.x >> 5)) ? sm[threadIdx.x] : 0.0f;
        #pragma unroll
        for (int o = 16; o; o >>= 1) m = fmaxf(m, __shfl_xor_sync(0xFFFFFFFFu, m, o));
        if (threadIdx.x == 0) atomicMax(&g_amax_bits, __float_as_uint(m));
    }
}

// ---------------- phase 2: quantize to fp8 bytes -----------------------------
__device__ __forceinline__ uint8_t to_e4m3(float v) {
    __nv_fp8_e4m3 q(v);                 // RN + satfinite == clip(+-448) + round in ref
    return *reinterpret_cast<uint8_t*>(&q);
}

__global__ void quant_a_kernel(const float* __restrict__ x) {
    int i = blockIdx.x * blockDim.x + threadIdx.x;  // float4 index
    float amax = fmaxf(__uint_as_float(g_amax_bits), 1e-12f);
    float scale = 448.0f / amax;
    float4 v = ((const float4*)x)[i];
    uint32_t o = (uint32_t)to_e4m3(v.x * scale)
               | ((uint32_t)to_e4m3(v.y * scale) << 8)
               | ((uint32_t)to_e4m3(v.z * scale) << 16)
               | ((uint32_t)to_e4m3(v.w * scale) << 24);
    ((uint32_t*)g_qa)[i] = o;
}

__global__ void quant_b_kernel(const float* __restrict__ w) {
    int i = blockIdx.x * blockDim.x + threadIdx.x;  // float4 index
    float4 v = ((const float4*)w)[i];
    // weight values already on the fp8 grid -> conversion exact
    uint32_t o = (uint32_t)to_e4m3(v.x)
               | ((uint32_t)to_e4m3(v.y) << 8)
               | ((uint32_t)to_e4m3(v.z) << 16)
               | ((uint32_t)to_e4m3(v.w) << 24);
    ((uint32_t*)g_qb)[i] = o;
}

// ---------------- phase 3: GEMM (fp8 mma.sync, cp.async pipeline) ------------
// SMEM stage layout: A tile [128 rows x 80B], then B tile [128 rows x 80B].
// Each row holds 64 fp8 (K chunk), viewed by ldmatrix as 32 b16 elements.

__global__ __launch_bounds__(256, 2)
void gemm_kernel(const float* __restrict__ wscale, const float* __restrict__ bias,
                 float* __restrict__ out) {
    extern __shared__ char smem[];
    const uint32_t s0 = smem_u32(smem);

    const int tid = threadIdx.x;
    const int wid = tid >> 5, lane = tid & 31;
    const int warp_m = wid >> 1, warp_n = wid & 1;   // 4 x 2 warps, 32x64 warp tile
    const int ntile = blockIdx.x, mtile = blockIdx.y;
    const int quad = lane >> 3, l8 = lane & 7;

    const uint8_t* Ag = g_qa + (size_t)mtile * BM * KDIM;
    const uint8_t* Bg = g_qb + (size_t)ntile * BN * KDIM;

    // cp.async mapping: each tile = 128 rows x 4 (16B chunks) = 512 chunks;
    // 256 threads x 2 chunks per tile.
    const int c0 = tid, c1 = tid + 256;
    const int ar0 = c0 >> 2, ac0 = c0 & 3;
    const int ar1 = c1 >> 2, ac1 = c1 & 3;
    const uint32_t sOff0 = (uint32_t)(ar0 * ROWB + ac0 * 16);
    const uint32_t sOff1 = (uint32_t)(ar1 * ROWB + ac1 * 16);

    // ldmatrix per-thread base offsets within a stage
    // A x4: quad&1 -> +8 row group is wrong for A; use standard A frag order:
    //   lanes 0-7: rows 0-7 k-low | 8-15: rows 8-15 k-low | 16-23: rows 0-7 k-high | 24-31: rows 8-15 k-high
    uint32_t aoff[2], boff[4];
    #pragma unroll
    for (int i = 0; i < 2; i++)
        aoff[i] = (uint32_t)((warp_m * 32 + i * 16 + (quad & 1) * 8 + l8) * ROWB
                             + (quad >> 1) * 16);
    // B x4: lanes 0-7: n rows 0-7 k-low | 8-15: rows 0-7 k-high | 16-23: rows 8-15 k-low | 24-31: rows 8-15 k-high
    #pragma unroll
    for (int j = 0; j < 4; j++)
        boff[j] = (uint32_t)(BM * ROWB
                             + (warp_n * 64 + j * 16 + (quad >> 1) * 8 + l8) * ROWB
                             + (quad & 1) * 16);

    float acc[2][8][4];
    #pragma unroll
    for (int mi = 0; mi < 2; mi++)
        #pragma unroll
        for (int ni = 0; ni < 8; ni++)
            #pragma unroll
            for (int r = 0; r < 4; r++) acc[mi][ni][r] = 0.0f;

    // ---- prologue: fill STAGES-1 stages
    #pragma unroll
    for (int st = 0; st < STAGES - 1; st++) {
        uint32_t sb = s0 + st * STAGE_BYTES;
        const uint8_t* ga = Ag + st * BK;
        const uint8_t* gb = Bg + st * BK;
        CP_ASYNC16(sb + sOff0, ga + (size_t)ar0 * KDIM + ac0 * 16);
        CP_ASYNC16(sb + sOff1, ga + (size_t)ar1 * KDIM + ac1 * 16);
        CP_ASYNC16(sb + (uint32_t)(BM * ROWB) + sOff0, gb + (size_t)ar0 * KDIM + ac0 * 16);
        CP_ASYNC16(sb + (uint32_t)(BM * ROWB) + sOff1, gb + (size_t)ar1 * KDIM + ac1 * 16);
        CP_COMMIT();
    }

    // ---- mainloop
    #pragma unroll 1
    for (int it = 0; it < KITERS; ++it) {
        CP_WAIT(STAGES - 2);
        __syncthreads();

        {   // issue loads for stage it+STAGES-1
            int lt = it + STAGES - 1;
            if (lt < KITERS) {
                uint32_t sb = s0 + (lt % STAGES) * STAGE_BYTES;
                const uint8_t* ga = Ag + lt * BK;
                const uint8_t* gb = Bg + lt * BK;
                CP_ASYNC16(sb + sOff0, ga + (size_t)ar0 * KDIM + ac0 * 16);
                CP_ASYNC16(sb + sOff1, ga + (size_t)ar1 * KDIM + ac1 * 16);
                CP_ASYNC16(sb + (uint32_t)(BM * ROWB) + sOff0, gb + (size_t)ar0 * KDIM + ac0 * 16);
                CP_ASYNC16(sb + (uint32_t)(BM * ROWB) + sOff1, gb + (size_t)ar1 * KDIM + ac1 * 16);
            }
            CP_COMMIT();   // keep wait_group counting uniform at the tail
        }

        uint32_t sb = s0 + (it % STAGES) * STAGE_BYTES;
        #pragma unroll
        for (int s = 0; s < 2; s++) {          // two k32 steps per BK=64
            uint32_t a[2][4], b[4][4];
            #pragma unroll
            for (int i = 0; i < 2; i++)
                LDSM_X4(a[i][0], a[i][1], a[i][2], a[i][3], sb + aoff[i] + s * 32);
            #pragma unroll
            for (int j = 0; j < 4; j++)
                LDSM_X4(b[j][0], b[j][1], b[j][2], b[j][3], sb + boff[j] + s * 32);
            #pragma unroll
            for (int mi = 0; mi < 2; mi++)
                #pragma unroll
                for (int ni = 0; ni < 8; ni++)
                    MMA16832(acc[mi][ni], a[mi], b[ni >> 1][(ni & 1) * 2],
                             b[ni >> 1][(ni & 1) * 2 + 1]);
        }
        __syncthreads();
    }

    // ---- epilogue: out = acc * (a_scale * w_scale) + bias
    float amax = fmaxf(__uint_as_float(g_amax_bits), 1e-12f);
    float comb = (amax / 448.0f) * wscale[0];

    const int gid = lane >> 2;
    const int lq = lane & 3;
    #pragma unroll
    for (int mi = 0; mi < 2; mi++) {
        int r0 = mtile * BM + warp_m * 32 + mi * 16 + gid;
        #pragma unroll
        for (int ni = 0; ni < 8; ni++) {
            int colg = ntile * BN + warp_n * 64 + ni * 8 + lq * 2;
            float2 bb = *(const float2*)(bias + colg);
            float2 o0, o1;
            o0.x = acc[mi][ni][0] * comb + bb.x;
            o0.y = acc[mi][ni][1] * comb + bb.y;
            o1.x = acc[mi][ni][2] * comb + bb.x;
            o1.y = acc[mi][ni][3] * comb + bb.y;
            *(float2*)(out + (size_t)r0 * NDIM + colg) = o0;
            *(float2*)(out + (size_t)(r0 + 8) * NDIM + colg) = o1;
        }
    }
}

// ---------------- launch -----------------------------------------------------
extern "C" void kernel_launch(void* const* d_in, const int* in_sizes, int n_in,
                              void* d_out, int out_size) {
    const float* input = nullptr;
    const float* qweight = nullptr;
    const float* wscale = nullptr;
    const float* bias = nullptr;
    for (int i = 0; i < n_in; i++) {
        long long s = in_sizes[i];
        if (s == (long long)MDIM * KDIM) input = (const float*)d_in[i];
        else if (s == (long long)NDIM * KDIM) qweight = (const float*)d_in[i];
        else if (s == 1) wscale = (const float*)d_in[i];
        else if (s == NDIM) bias = (const float*)d_in[i];
    }
    float* out = (float*)d_out;

    cudaFuncSetAttribute(gemm_kernel, cudaFuncAttributeMaxDynamicSharedMemorySize,
                         GEMM_SMEM);

    zero_kernel<<<1, 1>>>();
    amax_kernel<<<1024, 256>>>(input, MDIM * KDIM / 4);
    quant_a_kernel<<<MDIM * KDIM / 4 / 256, 256>>>(input);
    quant_b_kernel<<<NDIM * KDIM / 4 / 256, 256>>>(qweight);

    dim3 grid(NDIM / BN, MDIM / BM);   // ntile fastest: weight tiles stay L2-resident
    gemm_kernel<<<grid, 256, GEMM_SMEM>>>(wscale, bias, out);
}